// round 1
// baseline (speedup 1.0000x reference)
#include <cuda_runtime.h>

#define BB 64
#define TT 512
#define DD 256
#define HH 512
#define NCL 16            // clusters
#define CLC 8             // CTAs per cluster
#define BPC 4             // batches per cluster
#define JPC 64            // columns per CTA

// Scratch (module-static allocation; no runtime allocs)
__device__ float  g_xproj[(size_t)BB * TT * HH];       // 64 MB
__device__ float  g_hbuf[NCL][2][HH][BPC];             // ping-pong h, [k][b] layout
__device__ float2 g_part[NCL][CLC][BPC];               // LN partial (sum, sumsq)

__device__ __forceinline__ void cluster_sync_() {
    asm volatile("barrier.cluster.arrive.aligned;\n\t"
                 "barrier.cluster.wait.aligned;\n" ::: "memory");
}

// ---------------------------------------------------------------------------
// Kernel 1: xproj[B*T, H] = inputs[B*T, D] @ Wx[D, H] + b
// Tiles: BM=128, BN=64, BK=16; 256 threads; 8x4 outputs/thread.
// ---------------------------------------------------------------------------
__global__ void __launch_bounds__(256) xproj_kernel(
    const float* __restrict__ A, const float* __restrict__ Wx,
    const float* __restrict__ bias) {
    __shared__ float As[16][128];
    __shared__ float Bs[16][64];

    const int tid = threadIdx.x;
    const int bm  = blockIdx.x * 128;
    const int bn  = blockIdx.y * 64;
    const int tx  = tid & 15;   // column group (4 cols)
    const int ty  = tid >> 4;   // row group (8 rows)

    float acc[8][4];
#pragma unroll
    for (int i = 0; i < 8; ++i)
#pragma unroll
        for (int j = 0; j < 4; ++j) acc[i][j] = 0.f;

    const int m0 = tid >> 2;    // 0..63
    const int q  = tid & 3;     // float4 index within 16-float k-tile
    const int kb = tid >> 4;    // 0..15
    const int jb = tid & 15;    // 0..15

    for (int kt = 0; kt < 16; ++kt) {
        float4 a0 = __ldg((const float4*)(A + (size_t)(bm + m0) * DD + kt * 16) + q);
        float4 a1 = __ldg((const float4*)(A + (size_t)(bm + m0 + 64) * DD + kt * 16) + q);
        float4 bv = __ldg((const float4*)(Wx + (size_t)(kt * 16 + kb) * HH + bn) + jb);
        __syncthreads();
        As[q * 4 + 0][m0] = a0.x; As[q * 4 + 1][m0] = a0.y;
        As[q * 4 + 2][m0] = a0.z; As[q * 4 + 3][m0] = a0.w;
        As[q * 4 + 0][m0 + 64] = a1.x; As[q * 4 + 1][m0 + 64] = a1.y;
        As[q * 4 + 2][m0 + 64] = a1.z; As[q * 4 + 3][m0 + 64] = a1.w;
        *(float4*)&Bs[kb][jb * 4] = bv;
        __syncthreads();
#pragma unroll
        for (int k = 0; k < 16; ++k) {
            float ar[8], br[4];
            *(float4*)&ar[0] = *(const float4*)&As[k][ty * 8];
            *(float4*)&ar[4] = *(const float4*)&As[k][ty * 8 + 4];
            *(float4*)&br[0] = *(const float4*)&Bs[k][tx * 4];
#pragma unroll
            for (int i = 0; i < 8; ++i)
#pragma unroll
                for (int j = 0; j < 4; ++j)
                    acc[i][j] = fmaf(ar[i], br[j], acc[i][j]);
        }
    }

    float4 bb = __ldg((const float4*)(bias + bn) + tx);
#pragma unroll
    for (int i = 0; i < 8; ++i) {
        float4 v;
        v.x = acc[i][0] + bb.x; v.y = acc[i][1] + bb.y;
        v.z = acc[i][2] + bb.z; v.w = acc[i][3] + bb.w;
        *(float4*)&g_xproj[(size_t)(bm + ty * 8 + i) * HH + bn + tx * 4] = v;
    }
}

// ---------------------------------------------------------------------------
// Kernel 2: persistent recurrent scan.
// Grid = 128 CTAs, clusters of 8. Cluster cl owns batches [4cl, 4cl+4);
// CTA rank owns columns [64*rank, 64*rank+64). Wh[:, cols] (128KB) lives in
// SMEM for the entire scan. Per step: z = xp_t + h@Wh, LN stats exchanged
// cluster-wide via L2 (.cg) + cluster.sync, tanh, h exchanged via L2.
// ---------------------------------------------------------------------------
#define SCAN_SMEM ((32768 + 2048 + 1024 + 16 + 64 + 64 + 64) * 4)

__global__ void __cluster_dims__(8, 1, 1) __launch_bounds__(256, 1)
scan_kernel(const float* __restrict__ h0, const float* __restrict__ Wh,
            const float* __restrict__ gamma, const float* __restrict__ beta,
            float* __restrict__ out) {
    extern __shared__ float smf[];
    float* Wh_s  = smf;                  // [512][64]
    float* h_s   = smf + 32768;          // [512][4]  (k-major, b fast)
    float* red   = smf + 32768 + 2048;   // [4 b][4 kc][64 j]
    float* wred  = red + 1024;           // [8 warps][2]
    float* spart = wred + 16;            // [4 b][8 cta][2]
    float* gam_s = spart + 64;           // [64]
    float* bet_s = gam_s + 64;           // [64]

    const int tid   = threadIdx.x;
    const int rank  = blockIdx.x & 7;
    const int cl    = blockIdx.x >> 3;
    const int jbase = rank * JPC;
    const int bbase = cl * BPC;

    // Prologue: Wh column-slice -> SMEM (once, reused 512 steps)
    for (int i = tid; i < 512 * 16; i += 256) {
        int k = i >> 4, j4 = i & 15;
        float4 v = __ldg((const float4*)(Wh + (size_t)k * HH + jbase) + j4);
        *(float4*)&Wh_s[(k << 6) + (j4 << 2)] = v;
    }
    if (tid < 64) { gam_s[tid] = gamma[jbase + tid]; bet_s[tid] = beta[jbase + tid]; }
    for (int i = tid; i < 2048; i += 256) {          // h_s[k][b] = h0[bbase+b][k]
        int k = i >> 2, b = i & 3;
        h_s[i] = h0[(size_t)(bbase + b) * HH + k];
    }
    __syncthreads();

    const int j1 = tid & 63, kc = tid >> 6;   // phase 1: (col, k-chunk)
    const int b2 = tid >> 6, j2 = tid & 63;   // phase 2: (batch, col)
    const int k0 = kc << 7;
    const float4* h4 = (const float4*)h_s;

    for (int t = 0; t < TT; ++t) {
        // prefetch this thread's xproj element (used after reduction)
        float xp = __ldcg(&g_xproj[((size_t)(bbase + b2) * TT + t) * HH + jbase + j2]);

        // phase 1: partial z over this k-chunk, all 4 batches
        float a0 = 0.f, a1 = 0.f, a2 = 0.f, a3 = 0.f;
#pragma unroll 8
        for (int kk = 0; kk < 128; ++kk) {
            int k = k0 + kk;
            float  w  = Wh_s[(k << 6) + j1];  // 32 banks, conflict-free
            float4 hv = h4[k];                // broadcast
            a0 = fmaf(hv.x, w, a0);
            a1 = fmaf(hv.y, w, a1);
            a2 = fmaf(hv.z, w, a2);
            a3 = fmaf(hv.w, w, a3);
        }
        red[(kc << 6) + j1]       = a0;
        red[256 + (kc << 6) + j1] = a1;
        red[512 + (kc << 6) + j1] = a2;
        red[768 + (kc << 6) + j1] = a3;
        __syncthreads();

        // phase 2: z for (b2, j2), LN partial sums over this CTA's 64 cols
        float z = xp + red[(b2 << 8) + j2]       + red[(b2 << 8) + 64 + j2]
                     + red[(b2 << 8) + 128 + j2] + red[(b2 << 8) + 192 + j2];
        float s = z, qs = z * z;
#pragma unroll
        for (int o = 16; o > 0; o >>= 1) {
            s  += __shfl_xor_sync(0xffffffffu, s, o);
            qs += __shfl_xor_sync(0xffffffffu, qs, o);
        }
        const int warp = tid >> 5, lane = tid & 31;
        if (lane == 0) { wred[warp * 2] = s; wred[warp * 2 + 1] = qs; }
        __syncthreads();
        if (tid < 4) {   // batch = tid; combine its 2 warps; publish to cluster
            float ss = wred[tid * 4]     + wred[tid * 4 + 2];
            float qq = wred[tid * 4 + 1] + wred[tid * 4 + 3];
            __stcg(&g_part[cl][rank][tid], make_float2(ss, qq));
        }
        cluster_sync_();   // (A) stats visible cluster-wide

        if (tid < 32) {
            int c = tid >> 2, bsel = tid & 3;
            float2 v = __ldcg(&g_part[cl][c][bsel]);
            spart[(bsel << 4) + c * 2]     = v.x;
            spart[(bsel << 4) + c * 2 + 1] = v.y;
        }
        __syncthreads();

        float ssum = 0.f, qsum = 0.f;
#pragma unroll
        for (int c = 0; c < 8; ++c) {
            ssum += spart[(b2 << 4) + 2 * c];
            qsum += spart[(b2 << 4) + 2 * c + 1];
        }
        float mean = ssum * (1.0f / 512.0f);
        float var  = qsum * (1.0f / 512.0f) - mean * mean;
        float hval = tanhf((z - mean) * rsqrtf(var + 1e-3f) * gam_s[j2] + bet_s[j2]);

        out[((size_t)(bbase + b2) * TT + t) * HH + jbase + j2] = hval;
        __stcg(&g_hbuf[cl][(t + 1) & 1][jbase + j2][b2], hval);
        cluster_sync_();   // (B) h(t) visible cluster-wide

        if (t < TT - 1) {  // reload full h into SMEM for next step
            const float4* hb = (const float4*)&g_hbuf[cl][(t + 1) & 1][0][0];
            float4 v0 = __ldcg(hb + tid);
            float4 v1 = __ldcg(hb + 256 + tid);
            ((float4*)h_s)[tid]       = v0;
            ((float4*)h_s)[tid + 256] = v1;
            __syncthreads();
        }
    }
}

// ---------------------------------------------------------------------------
extern "C" void kernel_launch(void* const* d_in, const int* in_sizes, int n_in,
                              void* d_out, int out_size) {
    const float* inputs = (const float*)d_in[0];  // [64,512,256]
    const float* h0     = (const float*)d_in[1];  // [64,512]
    const float* Wx     = (const float*)d_in[2];  // [256,512]
    const float* Wh     = (const float*)d_in[3];  // [512,512]
    const float* bias   = (const float*)d_in[4];  // [512]
    const float* gamma  = (const float*)d_in[5];  // [512]
    const float* beta   = (const float*)d_in[6];  // [512]
    float* out = (float*)d_out;                   // [64,512,512]

    cudaFuncSetAttribute(scan_kernel,
                         cudaFuncAttributeMaxDynamicSharedMemorySize, SCAN_SMEM);

    dim3 g1(BB * TT / 128, HH / 64);
    xproj_kernel<<<g1, 256>>>(inputs, Wx, bias);
    scan_kernel<<<NCL * CLC, 256, SCAN_SMEM>>>(h0, Wh, gamma, beta, out);
}

// round 2
// speedup vs baseline: 1.2402x; 1.2402x over previous
#include <cuda_runtime.h>

#define BB 64
#define TT 512
#define DD 256
#define HH 512
#define NCL 16            // clusters
#define CLC 8             // CTAs per cluster
#define BPC 4             // batches per cluster
#define JPC 64            // columns per CTA

typedef unsigned long long ull;

// Scratch (module-static; no runtime allocs)
__device__ float  g_xproj[(size_t)BB * TT * HH];       // 64 MB
__device__ float  g_hbuf[NCL][2][HH][BPC];             // ping-pong h, [k][b]
__device__ float2 g_part[NCL][CLC][BPC];               // LN partials (sum, sumsq)

__device__ __forceinline__ void cluster_sync_() {
    asm volatile("barrier.cluster.arrive.aligned;\n\t"
                 "barrier.cluster.wait.aligned;\n" ::: "memory");
}
__device__ __forceinline__ void ffma2(ull& acc, ull a, ull b) {
    asm volatile("fma.rn.f32x2 %0, %1, %2, %0;" : "+l"(acc) : "l"(a), "l"(b));
}
__device__ __forceinline__ ull pack2(float x, float y) {
    ull r; asm("mov.b64 %0, {%1, %2};" : "=l"(r) : "f"(x), "f"(y)); return r;
}
__device__ __forceinline__ float2 unpack2(ull v) {
    float2 r; asm("mov.b64 {%0, %1}, %2;" : "=f"(r.x), "=f"(r.y) : "l"(v)); return r;
}

// ---------------------------------------------------------------------------
// Kernel 1: xproj[B*T, H] = inputs[B*T, D] @ Wx[D, H] + b
// BM=128, BN=64, BK=16; 256 threads; 8x4 outputs/thread via f32x2 row pairs.
// ---------------------------------------------------------------------------
__global__ void __launch_bounds__(256) xproj_kernel(
    const float* __restrict__ A, const float* __restrict__ Wx,
    const float* __restrict__ bias) {
    __shared__ float As[16][128];
    __shared__ float Bs[16][64];

    const int tid = threadIdx.x;
    const int bm  = blockIdx.x * 128;
    const int bn  = blockIdx.y * 64;
    const int tx  = tid & 15;   // column group (4 cols)
    const int ty  = tid >> 4;   // row group (8 rows, packed as 4 pairs)

    ull acc[4][4];              // [row-pair][col], each = {row_even, row_odd}
#pragma unroll
    for (int p = 0; p < 4; ++p)
#pragma unroll
        for (int j = 0; j < 4; ++j) acc[p][j] = 0ull;

    const int m0 = tid >> 2;
    const int q  = tid & 3;
    const int kb = tid >> 4;
    const int jb = tid & 15;

    for (int kt = 0; kt < 16; ++kt) {
        float4 a0 = __ldg((const float4*)(A + (size_t)(bm + m0) * DD + kt * 16) + q);
        float4 a1 = __ldg((const float4*)(A + (size_t)(bm + m0 + 64) * DD + kt * 16) + q);
        float4 bv = __ldg((const float4*)(Wx + (size_t)(kt * 16 + kb) * HH + bn) + jb);
        __syncthreads();
        As[q * 4 + 0][m0] = a0.x; As[q * 4 + 1][m0] = a0.y;
        As[q * 4 + 2][m0] = a0.z; As[q * 4 + 3][m0] = a0.w;
        As[q * 4 + 0][m0 + 64] = a1.x; As[q * 4 + 1][m0 + 64] = a1.y;
        As[q * 4 + 2][m0 + 64] = a1.z; As[q * 4 + 3][m0 + 64] = a1.w;
        *(float4*)&Bs[kb][jb * 4] = bv;
        __syncthreads();
#pragma unroll
        for (int k = 0; k < 16; ++k) {
            ulonglong2 a01 = *(const ulonglong2*)&As[k][ty * 8];     // pairs {r0r1},{r2r3}
            ulonglong2 a23 = *(const ulonglong2*)&As[k][ty * 8 + 4]; // pairs {r4r5},{r6r7}
            float4 bq = *(const float4*)&Bs[k][tx * 4];
            ull b0 = pack2(bq.x, bq.x), b1 = pack2(bq.y, bq.y);
            ull b2 = pack2(bq.z, bq.z), b3 = pack2(bq.w, bq.w);
            ffma2(acc[0][0], a01.x, b0); ffma2(acc[0][1], a01.x, b1);
            ffma2(acc[0][2], a01.x, b2); ffma2(acc[0][3], a01.x, b3);
            ffma2(acc[1][0], a01.y, b0); ffma2(acc[1][1], a01.y, b1);
            ffma2(acc[1][2], a01.y, b2); ffma2(acc[1][3], a01.y, b3);
            ffma2(acc[2][0], a23.x, b0); ffma2(acc[2][1], a23.x, b1);
            ffma2(acc[2][2], a23.x, b2); ffma2(acc[2][3], a23.x, b3);
            ffma2(acc[3][0], a23.y, b0); ffma2(acc[3][1], a23.y, b1);
            ffma2(acc[3][2], a23.y, b2); ffma2(acc[3][3], a23.y, b3);
        }
    }

    float4 bb = __ldg((const float4*)(bias + bn) + tx);
#pragma unroll
    for (int p = 0; p < 4; ++p) {
        float2 c0 = unpack2(acc[p][0]), c1 = unpack2(acc[p][1]);
        float2 c2 = unpack2(acc[p][2]), c3 = unpack2(acc[p][3]);
        float4 ve, vo;
        ve.x = c0.x + bb.x; ve.y = c1.x + bb.y; ve.z = c2.x + bb.z; ve.w = c3.x + bb.w;
        vo.x = c0.y + bb.x; vo.y = c1.y + bb.y; vo.z = c2.y + bb.z; vo.w = c3.y + bb.w;
        int row = bm + ty * 8 + p * 2;
        *(float4*)&g_xproj[(size_t)row * HH + bn + tx * 4]       = ve;
        *(float4*)&g_xproj[(size_t)(row + 1) * HH + bn + tx * 4] = vo;
    }
}

// ---------------------------------------------------------------------------
// Kernel 2: persistent recurrent scan, 512 threads/CTA.
// Cluster cl owns batches [4cl,4cl+4); CTA rank owns cols [64r, 64r+64).
// Wh[:,cols] (128KB) SMEM-resident for all 512 steps.
// Phase 1: thread = (col-pair jp 0..31, k-chunk kc 0..15 of 32), f32x2 FMA,
//          batches packed in pairs. Phase 2 (256 threads): z, LN, tanh.
// ---------------------------------------------------------------------------
#define F_WH    0
#define F_H     32768          // [512][4] floats
#define F_RED   (32768 + 2048) // float2 red2[(kc*2+bp)*64 + j] -> 4096 floats
#define F_WRED  (F_RED + 4096)
#define F_SPART (F_WRED + 16)
#define F_GAM   (F_SPART + 64)
#define F_BET   (F_GAM + 64)
#define SCAN_SMEM ((F_BET + 64) * 4)

__global__ void __cluster_dims__(8, 1, 1) __launch_bounds__(512, 1)
scan_kernel(const float* __restrict__ h0, const float* __restrict__ Wh,
            const float* __restrict__ gamma, const float* __restrict__ beta,
            float* __restrict__ out) {
    extern __shared__ float smf[];
    float* Wh_s  = smf + F_WH;
    float* h_s   = smf + F_H;
    float* redf  = smf + F_RED;
    float* wred  = smf + F_WRED;
    float* spart = smf + F_SPART;
    float* gam_s = smf + F_GAM;
    float* bet_s = smf + F_BET;

    const int tid   = threadIdx.x;
    const int rank  = blockIdx.x & 7;
    const int cl    = blockIdx.x >> 3;
    const int jbase = rank * JPC;
    const int bbase = cl * BPC;

    // Prologue
    for (int i = tid; i < 512 * 16; i += 512) {
        int k = i >> 4, j4 = i & 15;
        float4 v = __ldg((const float4*)(Wh + (size_t)k * HH + jbase) + j4);
        *(float4*)&Wh_s[(k << 6) + (j4 << 2)] = v;
    }
    if (tid < 64) { gam_s[tid] = gamma[jbase + tid]; bet_s[tid] = beta[jbase + tid]; }
    for (int i = tid; i < 2048; i += 512) {        // h_s[k][b] = h0[bbase+b][k]
        int k = i >> 2, b = i & 3;
        h_s[i] = h0[(size_t)(bbase + b) * HH + k];
    }
    __syncthreads();

    const int jp = tid & 31;          // column pair: cols 2jp, 2jp+1
    const int kc = tid >> 5;          // k chunk: [32kc, 32kc+32)
    const int b2 = (tid >> 6) & 3;    // phase-2 batch (tid < 256)
    const int j2 = tid & 63;          // phase-2 column
    const int bp = b2 >> 1, comp = b2 & 1;
    const ulonglong2* h2 = (const ulonglong2*)h_s;
    const float2* w2p = (const float2*)Wh_s;

    for (int t = 0; t < TT; ++t) {
        float xp = 0.f;
        if (tid < 256)
            xp = __ldcg(&g_xproj[((size_t)(bbase + b2) * TT + t) * HH + jbase + j2]);

        // ---- phase 1: partial z, f32x2 packed over batch pairs ----
        ull aj0b01 = 0, aj0b23 = 0, aj1b01 = 0, aj1b23 = 0;
        const int k0 = kc << 5;
#pragma unroll
        for (int kk = 0; kk < 32; ++kk) {
            int k = k0 + kk;
            float2 w2 = w2p[(k << 5) + jp];     // cols 2jp,2jp+1 : conflict-free
            ulonglong2 hp = h2[k];              // {b0,b1},{b2,b3} broadcast
            ull w00 = pack2(w2.x, w2.x);
            ull w11 = pack2(w2.y, w2.y);
            ffma2(aj0b01, hp.x, w00);
            ffma2(aj0b23, hp.y, w00);
            ffma2(aj1b01, hp.x, w11);
            ffma2(aj1b23, hp.y, w11);
        }
        // red2[(kc*2+bp)*64 + j]; adjacent cols -> one STS.128 each
        {
            ulonglong2 v01; v01.x = aj0b01; v01.y = aj1b01;
            ulonglong2 v23; v23.x = aj0b23; v23.y = aj1b23;
            *(ulonglong2*)&redf[((kc * 2 + 0) * 64 + 2 * jp) * 2] = v01;
            *(ulonglong2*)&redf[((kc * 2 + 1) * 64 + 2 * jp) * 2] = v23;
        }
        __syncthreads();

        // ---- phase 2 (tid < 256): z, LN stats ----
        float z = 0.f;
        if (tid < 256) {
            float s0 = 0.f, s1 = 0.f;
#pragma unroll
            for (int c = 0; c < 16; c += 2) {
                s0 += redf[((c * 2 + bp) * 64 + j2) * 2 + comp];
                s1 += redf[(((c + 1) * 2 + bp) * 64 + j2) * 2 + comp];
            }
            z = xp + s0 + s1;
            float s = z, qs = z * z;
#pragma unroll
            for (int o = 16; o > 0; o >>= 1) {
                s  += __shfl_xor_sync(0xffffffffu, s, o);
                qs += __shfl_xor_sync(0xffffffffu, qs, o);
            }
            if ((tid & 31) == 0) {
                int warp = tid >> 5;
                wred[warp * 2] = s; wred[warp * 2 + 1] = qs;
            }
        }
        __syncthreads();
        if (tid < 4) {
            float ss = wred[tid * 4]     + wred[tid * 4 + 2];
            float qq = wred[tid * 4 + 1] + wred[tid * 4 + 3];
            __stcg(&g_part[cl][rank][tid], make_float2(ss, qq));
        }
        cluster_sync_();   // (A) stats visible cluster-wide

        if (tid < 32) {
            int c = tid >> 2, bsel = tid & 3;
            float2 v = __ldcg(&g_part[cl][c][bsel]);
            spart[(bsel << 4) + c * 2]     = v.x;
            spart[(bsel << 4) + c * 2 + 1] = v.y;
        }
        __syncthreads();

        if (tid < 256) {
            float ssum = 0.f, qsum = 0.f;
#pragma unroll
            for (int c = 0; c < 8; ++c) {
                ssum += spart[(b2 << 4) + 2 * c];
                qsum += spart[(b2 << 4) + 2 * c + 1];
            }
            float mean = ssum * (1.0f / 512.0f);
            float var  = qsum * (1.0f / 512.0f) - mean * mean;
            float hval = tanhf((z - mean) * rsqrtf(var + 1e-3f) * gam_s[j2] + bet_s[j2]);
            __stcg(&g_hbuf[cl][(t + 1) & 1][jbase + j2][b2], hval);
            out[((size_t)(bbase + b2) * TT + t) * HH + jbase + j2] = hval;
        }
        cluster_sync_();   // (B) h(t) visible cluster-wide

        if (t < TT - 1) {  // reload full h into SMEM (512 float4s / 512 thr)
            const float4* hb = (const float4*)&g_hbuf[cl][(t + 1) & 1][0][0];
            ((float4*)h_s)[tid] = __ldcg(hb + tid);
            __syncthreads();
        }
    }
}

// ---------------------------------------------------------------------------
extern "C" void kernel_launch(void* const* d_in, const int* in_sizes, int n_in,
                              void* d_out, int out_size) {
    const float* inputs = (const float*)d_in[0];  // [64,512,256]
    const float* h0     = (const float*)d_in[1];  // [64,512]
    const float* Wx     = (const float*)d_in[2];  // [256,512]
    const float* Wh     = (const float*)d_in[3];  // [512,512]
    const float* bias   = (const float*)d_in[4];  // [512]
    const float* gamma  = (const float*)d_in[5];  // [512]
    const float* beta   = (const float*)d_in[6];  // [512]
    float* out = (float*)d_out;                   // [64,512,512]

    cudaFuncSetAttribute(scan_kernel,
                         cudaFuncAttributeMaxDynamicSharedMemorySize, SCAN_SMEM);

    dim3 g1(BB * TT / 128, HH / 64);
    xproj_kernel<<<g1, 256>>>(inputs, Wx, bias);
    scan_kernel<<<NCL * CLC, 512, SCAN_SMEM>>>(h0, Wh, gamma, beta, out);
}

// round 3
// speedup vs baseline: 1.4567x; 1.1746x over previous
#include <cuda_runtime.h>

#define BB 64
#define TT 512
#define DD 256
#define HH 512
#define NCL 16            // clusters
#define CLC 8             // CTAs per cluster
#define BPC 4             // batches per cluster
#define JPC 64            // columns per CTA

typedef unsigned long long ull;

// Scratch (module-static; no runtime allocs)
__device__ float  g_xproj[(size_t)BB * TT * HH];          // 64 MB
__device__ float  g_z[NCL][2][HH][BPC];                   // ping-pong z exchange
__device__ float2 g_part[NCL][2][CLC][BPC];               // ping-pong LN partials

__device__ __forceinline__ void cluster_sync_() {
    asm volatile("barrier.cluster.arrive.aligned;\n\t"
                 "barrier.cluster.wait.aligned;\n" ::: "memory");
}
__device__ __forceinline__ void ffma2(ull& acc, ull a, ull b) {
    asm volatile("fma.rn.f32x2 %0, %1, %2, %0;" : "+l"(acc) : "l"(a), "l"(b));
}
__device__ __forceinline__ ull pack2(float x, float y) {
    ull r; asm("mov.b64 %0, {%1, %2};" : "=l"(r) : "f"(x), "f"(y)); return r;
}
__device__ __forceinline__ float2 unpack2(ull v) {
    float2 r; asm("mov.b64 {%0, %1}, %2;" : "=f"(r.x), "=f"(r.y) : "l"(v)); return r;
}
// fast tanh: exact enough (~1e-7 abs) and ~7 instr
__device__ __forceinline__ float ftanh(float x) {
    float xc = fminf(fmaxf(x, -9.f), 9.f);
    float e  = __expf(2.f * xc);
    return 1.f - __fdividef(2.f, e + 1.f);
}

// ---------------------------------------------------------------------------
// Kernel 1: xproj[B*T, H] = inputs[B*T, D] @ Wx[D, H] + b  (f32x2 FMA)
// ---------------------------------------------------------------------------
__global__ void __launch_bounds__(256) xproj_kernel(
    const float* __restrict__ A, const float* __restrict__ Wx,
    const float* __restrict__ bias) {
    __shared__ float As[16][128];
    __shared__ float Bs[16][64];

    const int tid = threadIdx.x;
    const int bm  = blockIdx.x * 128;
    const int bn  = blockIdx.y * 64;
    const int tx  = tid & 15;
    const int ty  = tid >> 4;

    ull acc[4][4];
#pragma unroll
    for (int p = 0; p < 4; ++p)
#pragma unroll
        for (int j = 0; j < 4; ++j) acc[p][j] = 0ull;

    const int m0 = tid >> 2;
    const int q  = tid & 3;
    const int kb = tid >> 4;
    const int jb = tid & 15;

    for (int kt = 0; kt < 16; ++kt) {
        float4 a0 = __ldg((const float4*)(A + (size_t)(bm + m0) * DD + kt * 16) + q);
        float4 a1 = __ldg((const float4*)(A + (size_t)(bm + m0 + 64) * DD + kt * 16) + q);
        float4 bv = __ldg((const float4*)(Wx + (size_t)(kt * 16 + kb) * HH + bn) + jb);
        __syncthreads();
        As[q * 4 + 0][m0] = a0.x; As[q * 4 + 1][m0] = a0.y;
        As[q * 4 + 2][m0] = a0.z; As[q * 4 + 3][m0] = a0.w;
        As[q * 4 + 0][m0 + 64] = a1.x; As[q * 4 + 1][m0 + 64] = a1.y;
        As[q * 4 + 2][m0 + 64] = a1.z; As[q * 4 + 3][m0 + 64] = a1.w;
        *(float4*)&Bs[kb][jb * 4] = bv;
        __syncthreads();
#pragma unroll
        for (int k = 0; k < 16; ++k) {
            ulonglong2 a01 = *(const ulonglong2*)&As[k][ty * 8];
            ulonglong2 a23 = *(const ulonglong2*)&As[k][ty * 8 + 4];
            float4 bq = *(const float4*)&Bs[k][tx * 4];
            ull b0 = pack2(bq.x, bq.x), b1 = pack2(bq.y, bq.y);
            ull b2 = pack2(bq.z, bq.z), b3 = pack2(bq.w, bq.w);
            ffma2(acc[0][0], a01.x, b0); ffma2(acc[0][1], a01.x, b1);
            ffma2(acc[0][2], a01.x, b2); ffma2(acc[0][3], a01.x, b3);
            ffma2(acc[1][0], a01.y, b0); ffma2(acc[1][1], a01.y, b1);
            ffma2(acc[1][2], a01.y, b2); ffma2(acc[1][3], a01.y, b3);
            ffma2(acc[2][0], a23.x, b0); ffma2(acc[2][1], a23.x, b1);
            ffma2(acc[2][2], a23.x, b2); ffma2(acc[2][3], a23.x, b3);
            ffma2(acc[3][0], a23.y, b0); ffma2(acc[3][1], a23.y, b1);
            ffma2(acc[3][2], a23.y, b2); ffma2(acc[3][3], a23.y, b3);
        }
    }

    float4 bb = __ldg((const float4*)(bias + bn) + tx);
#pragma unroll
    for (int p = 0; p < 4; ++p) {
        float2 c0 = unpack2(acc[p][0]), c1 = unpack2(acc[p][1]);
        float2 c2 = unpack2(acc[p][2]), c3 = unpack2(acc[p][3]);
        float4 ve, vo;
        ve.x = c0.x + bb.x; ve.y = c1.x + bb.y; ve.z = c2.x + bb.z; ve.w = c3.x + bb.w;
        vo.x = c0.y + bb.x; vo.y = c1.y + bb.y; vo.z = c2.y + bb.z; vo.w = c3.y + bb.w;
        int row = bm + ty * 8 + p * 2;
        *(float4*)&g_xproj[(size_t)row * HH + bn + tx * 4]       = ve;
        *(float4*)&g_xproj[(size_t)(row + 1) * HH + bn + tx * 4] = vo;
    }
}

// ---------------------------------------------------------------------------
// Kernel 2: persistent scan, 512 threads/CTA, ONE cluster.sync per step.
// Exchange z (pre-LN) + LN partials through L2 (ping-pong by t&1); every CTA
// computes h = tanh(LN(z)) for ALL 512x4 entries into its own SMEM h_s.
// ---------------------------------------------------------------------------
#define F_WH    0
#define F_H     32768              // [512][4] floats (k-major, b fast)
#define F_RED   (32768 + 2048)     // 4096 floats
#define F_WRED  (F_RED + 4096)     // 16
#define F_STAT  (F_WRED + 16)      // 8 floats (float2[4]: mean, rstd)
#define SCAN_SMEM ((F_STAT + 8) * 4)

__global__ void __cluster_dims__(8, 1, 1) __launch_bounds__(512, 1)
scan_kernel(const float* __restrict__ h0, const float* __restrict__ Wh,
            const float* __restrict__ gamma, const float* __restrict__ beta,
            float* __restrict__ out) {
    extern __shared__ float smf[];
    float*  Wh_s  = smf + F_WH;
    float*  h_s   = smf + F_H;
    float*  redf  = smf + F_RED;
    float*  wred  = smf + F_WRED;
    float2* sstat = (float2*)(smf + F_STAT);

    const int tid   = threadIdx.x;
    const int rank  = blockIdx.x & 7;
    const int cl    = blockIdx.x >> 3;
    const int jbase = rank * JPC;
    const int bbase = cl * BPC;

    // Prologue: Wh column slice -> SMEM; h0 -> SMEM; per-thread gamma/beta
    for (int i = tid; i < 512 * 16; i += 512) {
        int k = i >> 4, j4 = i & 15;
        float4 v = __ldg((const float4*)(Wh + (size_t)k * HH + jbase) + j4);
        *(float4*)&Wh_s[(k << 6) + (j4 << 2)] = v;
    }
    {
        float4 hv;
        hv.x = h0[(size_t)(bbase + 0) * HH + tid];
        hv.y = h0[(size_t)(bbase + 1) * HH + tid];
        hv.z = h0[(size_t)(bbase + 2) * HH + tid];
        hv.w = h0[(size_t)(bbase + 3) * HH + tid];
        *(float4*)&h_s[tid * 4] = hv;
    }
    const float gmj = __ldg(&gamma[tid]);
    const float btj = __ldg(&beta[tid]);
    __syncthreads();

    const int jp = tid & 31;          // column pair 2jp, 2jp+1
    const int kc = tid >> 5;          // k chunk [32kc, 32kc+32)
    const int b2 = (tid >> 6) & 3;    // phase-2 batch (tid < 256)
    const int j2 = tid & 63;          // phase-2 column
    const int bp = b2 >> 1, comp = b2 & 1;
    const ulonglong2* h2 = (const ulonglong2*)h_s;
    const float2* w2p = (const float2*)Wh_s;
    const bool own = ((unsigned)(tid - jbase) < 64u);

    for (int t = 0; t < TT; ++t) {
        const int buf = t & 1;
        float xp = 0.f;
        if (tid < 256)
            xp = __ldcg(&g_xproj[((size_t)(bbase + b2) * TT + t) * HH + jbase + j2]);

        // ---- phase 1: matvec partials, f32x2 over batch pairs ----
        ull aj0b01 = 0, aj0b23 = 0, aj1b01 = 0, aj1b23 = 0;
        const int k0 = kc << 5;
#pragma unroll
        for (int kk = 0; kk < 32; ++kk) {
            int k = k0 + kk;
            float2 w2 = w2p[(k << 5) + jp];
            ulonglong2 hp = h2[k];
            ull w00 = pack2(w2.x, w2.x);
            ull w11 = pack2(w2.y, w2.y);
            ffma2(aj0b01, hp.x, w00);
            ffma2(aj0b23, hp.y, w00);
            ffma2(aj1b01, hp.x, w11);
            ffma2(aj1b23, hp.y, w11);
        }
        {
            ulonglong2 v01; v01.x = aj0b01; v01.y = aj1b01;
            ulonglong2 v23; v23.x = aj0b23; v23.y = aj1b23;
            *(ulonglong2*)&redf[((kc * 2 + 0) * 64 + 2 * jp) * 2] = v01;
            *(ulonglong2*)&redf[((kc * 2 + 1) * 64 + 2 * jp) * 2] = v23;
        }
        __syncthreads();

        // ---- phase 2 (tid < 256): z, publish z + LN warp partials ----
        if (tid < 256) {
            float s0 = 0.f, s1 = 0.f;
#pragma unroll
            for (int c = 0; c < 16; c += 2) {
                s0 += redf[((c * 2 + bp) * 64 + j2) * 2 + comp];
                s1 += redf[(((c + 1) * 2 + bp) * 64 + j2) * 2 + comp];
            }
            float z = xp + s0 + s1;
            __stcg(&g_z[cl][buf][jbase + j2][b2], z);
            float s = z, qs = z * z;
#pragma unroll
            for (int o = 16; o > 0; o >>= 1) {
                s  += __shfl_xor_sync(0xffffffffu, s, o);
                qs += __shfl_xor_sync(0xffffffffu, qs, o);
            }
            if ((tid & 31) == 0) {
                int warp = tid >> 5;
                wred[warp * 2] = s; wred[warp * 2 + 1] = qs;
            }
        }
        __syncthreads();
        if (tid < 4) {
            float ss = wred[tid * 4]     + wred[tid * 4 + 2];
            float qq = wred[tid * 4 + 1] + wred[tid * 4 + 3];
            __stcg(&g_part[cl][buf][rank][tid], make_float2(ss, qq));
        }
        cluster_sync_();   // single sync: z + partials visible cluster-wide

        // overlapped L2 reads: full z row-block + stat partials
        float4 zq = __ldcg((const float4*)&g_z[cl][buf][tid][0]);
        if (tid < 4) {
            float ss = 0.f, qq = 0.f;
#pragma unroll
            for (int c = 0; c < 8; ++c) {
                float2 p = __ldcg(&g_part[cl][buf][c][tid]);
                ss += p.x; qq += p.y;
            }
            float mean = ss * (1.0f / 512.0f);
            float var  = qq * (1.0f / 512.0f) - mean * mean;
            sstat[tid] = make_float2(mean, rsqrtf(var + 1e-3f));
        }
        __syncthreads();

        // every CTA computes h for ALL (j=tid, b=0..3) locally -> SMEM
        float2 st0 = sstat[0], st1 = sstat[1], st2 = sstat[2], st3 = sstat[3];
        float4 hq;
        hq.x = ftanh((zq.x - st0.x) * st0.y * gmj + btj);
        hq.y = ftanh((zq.y - st1.x) * st1.y * gmj + btj);
        hq.z = ftanh((zq.z - st2.x) * st2.y * gmj + btj);
        hq.w = ftanh((zq.w - st3.x) * st3.y * gmj + btj);
        *(float4*)&h_s[tid * 4] = hq;

        if (own) {   // write this CTA's 64 output columns
            out[((size_t)(bbase + 0) * TT + t) * HH + tid] = hq.x;
            out[((size_t)(bbase + 1) * TT + t) * HH + tid] = hq.y;
            out[((size_t)(bbase + 2) * TT + t) * HH + tid] = hq.z;
            out[((size_t)(bbase + 3) * TT + t) * HH + tid] = hq.w;
        }
        __syncthreads();   // h_s ready for next phase 1
    }
}

// ---------------------------------------------------------------------------
extern "C" void kernel_launch(void* const* d_in, const int* in_sizes, int n_in,
                              void* d_out, int out_size) {
    const float* inputs = (const float*)d_in[0];  // [64,512,256]
    const float* h0     = (const float*)d_in[1];  // [64,512]
    const float* Wx     = (const float*)d_in[2];  // [256,512]
    const float* Wh     = (const float*)d_in[3];  // [512,512]
    const float* bias   = (const float*)d_in[4];  // [512]
    const float* gamma  = (const float*)d_in[5];  // [512]
    const float* beta   = (const float*)d_in[6];  // [512]
    float* out = (float*)d_out;                   // [64,512,512]

    cudaFuncSetAttribute(scan_kernel,
                         cudaFuncAttributeMaxDynamicSharedMemorySize, SCAN_SMEM);

    dim3 g1(BB * TT / 128, HH / 64);
    xproj_kernel<<<g1, 256>>>(inputs, Wx, bias);
    scan_kernel<<<NCL * CLC, 512, SCAN_SMEM>>>(h0, Wh, gamma, beta, out);
}